// round 11
// baseline (speedup 1.0000x reference)
#include <cuda_runtime.h>
#include <cuda_bf16.h>
#include <math.h>

// ---------------------------------------------------------------------------
#define B_     2
#define T_     20
#define V_     256
#define TN     (T_ * V_)          // 5120
#define NROWS  (B_ * TN)         // 10240
#define HID    4
#define DQ     8
#define OUTD   5
#define CMAP   2048
#define HMAP   32
#define WMAP   32
#define NPIX   (HMAP * WMAP)     // 1024
#define CC     256

#define KSPLIT 128
#define KCHUNK (TN / KSPLIT)     // 40
#define QPT    4                 // queries per thread in k3
#define K3THR  128
#define QBLK   (K3THR * QPT)     // 512
#define NQB    (NROWS / QBLK)    // 20

#define C1SPLIT 64               // channel chunks (32 ch each) in k1f

// ---------------------------------------------------------------------------
__device__ float  g_cb[4];
__device__ float  g_pp[C1SPLIT * 4 * NPIX];
__device__ float4 g_pcomp4[NPIX];
__device__ float4 g_ABG[NROWS];               // (alpha,beta,gamma)*-log2e, pad
__device__ float2 g_UW[NROWS];                // pos-encoded (xr0, xr1)
__device__ float4 g_part[KSPLIT * NROWS];     // (T0,T1,T2,pad) partials

// ---------------------------------------------------------------------------
__device__ __forceinline__ float ex2f(float x) {
    float r; asm("ex2.approx.f32 %0, %1;" : "=f"(r) : "f"(x)); return r;
}
__device__ __forceinline__ float rcpf(float x) {
    float r; asm("rcp.approx.f32 %0, %1;" : "=f"(r) : "f"(x)); return r;
}
__device__ __forceinline__ float fsigm(float x) { return rcpf(1.f + ex2f(-1.44269504f * x)); }
__device__ __forceinline__ float ftanh(float x) { return 1.f - 2.f * rcpf(ex2f(2.88539008f * x) + 1.f); }

// ---------------------------------------------------------------------------
// K1f: fused Weff + pcomp partial. grid(64) x 256.
// ---------------------------------------------------------------------------
__global__ __launch_bounds__(256) void k1f(const float* __restrict__ W_fuse,
                                           const float* __restrict__ W_comp,
                                           const float* __restrict__ b_comp,
                                           const float* __restrict__ metadata) {
    __shared__ float sWfl[4 * 256];   // W_fuse[:, 4:260]
    __shared__ float sW8[8][128];     // per-warp Weff partials
    __shared__ float sw[128];         // Weff[h][cl] for this slice
    int tid = threadIdx.x, ci = blockIdx.x;
    int warp = tid >> 5, lane = tid & 31;

    for (int i = tid; i < 4 * 256; i += 256) {
        int h = i >> 8, cc = i & 255;
        sWfl[i] = W_fuse[h * 260 + 4 + cc];
    }
    __syncthreads();

    {
        float a0 = 0.f, a1 = 0.f, a2 = 0.f, a3 = 0.f;
        const float* base = W_comp + ci * 32 + lane;
#pragma unroll
        for (int k = 0; k < 32; k++) {
            int cc = warp * 32 + k;
            float wv = base[cc * CMAP];
            a0 += sWfl[cc]       * wv;
            a1 += sWfl[256 + cc] * wv;
            a2 += sWfl[512 + cc] * wv;
            a3 += sWfl[768 + cc] * wv;
        }
        sW8[warp][0 * 32 + lane] = a0;
        sW8[warp][1 * 32 + lane] = a1;
        sW8[warp][2 * 32 + lane] = a2;
        sW8[warp][3 * 32 + lane] = a3;
    }
    __syncthreads();

    if (tid < 128) {
        float s = 0.f;
#pragma unroll
        for (int wp = 0; wp < 8; wp++) s += sW8[wp][tid];
        sw[tid] = s;
    }

    if (ci == 0 && warp == 4) {
        float p0 = 0.f, p1 = 0.f, p2 = 0.f, p3 = 0.f;
        for (int cc = lane; cc < CC; cc += 32) {
            float bv = b_comp[cc];
            p0 += sWfl[cc]       * bv;
            p1 += sWfl[256 + cc] * bv;
            p2 += sWfl[512 + cc] * bv;
            p3 += sWfl[768 + cc] * bv;
        }
#pragma unroll
        for (int o = 16; o > 0; o >>= 1) {
            p0 += __shfl_down_sync(0xffffffffu, p0, o);
            p1 += __shfl_down_sync(0xffffffffu, p1, o);
            p2 += __shfl_down_sync(0xffffffffu, p2, o);
            p3 += __shfl_down_sync(0xffffffffu, p3, o);
        }
        if (lane == 0) { g_cb[0] = p0; g_cb[1] = p1; g_cb[2] = p2; g_cb[3] = p3; }
    }
    __syncthreads();

    const float4* m4 = (const float4*)metadata;
    float4 a0 = make_float4(0, 0, 0, 0), a1 = a0, a2 = a0, a3 = a0;
#pragma unroll 8
    for (int cl = 0; cl < 32; cl++) {
        float4 m = m4[(ci * 32 + cl) * 256 + tid];
        float w0 = sw[cl], w1 = sw[32 + cl], w2 = sw[64 + cl], w3 = sw[96 + cl];
        a0.x += w0 * m.x; a0.y += w0 * m.y; a0.z += w0 * m.z; a0.w += w0 * m.w;
        a1.x += w1 * m.x; a1.y += w1 * m.y; a1.z += w1 * m.z; a1.w += w1 * m.w;
        a2.x += w2 * m.x; a2.y += w2 * m.y; a2.z += w2 * m.z; a2.w += w2 * m.w;
        a3.x += w3 * m.x; a3.y += w3 * m.y; a3.z += w3 * m.z; a3.w += w3 * m.w;
    }
    float4* pp4 = (float4*)g_pp;
    pp4[(ci * 4 + 0) * 256 + tid] = a0;
    pp4[(ci * 4 + 1) * 256 + tid] = a1;
    pp4[(ci * 4 + 2) * 256 + tid] = a2;
    pp4[(ci * 4 + 3) * 256 + tid] = a3;
}

// ---------------------------------------------------------------------------
// K1b: reduce 64 partials + bias. grid(4) x 256.
// ---------------------------------------------------------------------------
__global__ __launch_bounds__(256) void k1b_reduce() {
    int pix = blockIdx.x * 256 + threadIdx.x;
    float s0 = g_cb[0], s1 = g_cb[1], s2 = g_cb[2], s3 = g_cb[3];
#pragma unroll 8
    for (int ci = 0; ci < C1SPLIT; ci++) {
        s0 += g_pp[(ci * 4 + 0) * NPIX + pix];
        s1 += g_pp[(ci * 4 + 1) * NPIX + pix];
        s2 += g_pp[(ci * 4 + 2) * NPIX + pix];
        s3 += g_pp[(ci * 4 + 3) * NPIX + pix];
    }
    g_pcomp4[pix] = make_float4(s0, s1, s2, s3);
}

// ---------------------------------------------------------------------------
// K2: per-row pipeline, no smem staging (weights are warp-uniform L1-resident
// loads). grid(80) x 128.
// ---------------------------------------------------------------------------
__global__ __launch_bounds__(128) void k2_rows(
        const float* __restrict__ x,
        const float* __restrict__ coords,
        const float* __restrict__ W_ih,
        const float* __restrict__ b_ih,
        const float* __restrict__ b_hh,
        const float* __restrict__ W_fuse,
        const float* __restrict__ b_fuse,
        const float* __restrict__ W_fc,
        const float* __restrict__ b_fc,
        const float* __restrict__ W_fc2,
        const float* __restrict__ b_fc2) {
    int tid = threadIdx.x;
    int r = blockIdx.x * 128 + tid;
    int b = r / TN;
    int p = r - b * TN;
    int t = p / V_;
    int v = p - t * V_;

    float2 xin = ((const float2*)x)[r];
    float cx = coords[((b * 2 + 0) * T_ + t) * V_ + v];
    float cy = coords[((b * 2 + 1) * T_ + t) * V_ + v];

    float tf  = (float)t;
    float xr0 = xin.x + __sinf(tf);
    float xr1 = xin.y + __cosf(tf);
    g_UW[r] = make_float2(xr0, xr1);

    float X[HID];
#pragma unroll
    for (int h = 0; h < HID; h++) {
        int ji = h, jg = 8 + h, jo = 12 + h;
        float gi = W_ih[ji * 2] * xr0 + W_ih[ji * 2 + 1] * xr1 + b_ih[ji] + b_hh[ji];
        float gg = W_ih[jg * 2] * xr0 + W_ih[jg * 2 + 1] * xr1 + b_ih[jg] + b_hh[jg];
        float go = W_ih[jo * 2] * xr0 + W_ih[jo * 2 + 1] * xr1 + b_ih[jo] + b_hh[jo];
        float cst = fsigm(gi) * ftanh(gg);
        X[h] = fsigm(go) * ftanh(cst);
    }

    float fx = cx * (1.f / 16.f) - 0.5f;
    float fy = cy * (1.f / 16.f) - 0.5f;
    float x0f = floorf(fx), y0f = floorf(fy);
    int ix0 = (int)x0f, iy0 = (int)y0f;
    float wx1 = fx - x0f, wx0 = 1.f - wx1;
    float wy1 = fy - y0f, wy0 = 1.f - wy1;

    float l0 = 0.f, l1 = 0.f, l2 = 0.f, l3 = 0.f;
#pragma unroll
    for (int cyi = 0; cyi < 2; cyi++) {
#pragma unroll
        for (int cxi = 0; cxi < 2; cxi++) {
            int iy = iy0 + cyi, ix = ix0 + cxi;
            if (iy >= 0 && iy < HMAP && ix >= 0 && ix < WMAP) {
                float w = (cyi ? wy1 : wy0) * (cxi ? wx1 : wx0);
                float4 pv = g_pcomp4[iy * WMAP + ix];
                l0 += w * pv.x; l1 += w * pv.y; l2 += w * pv.z; l3 += w * pv.w;
            }
        }
    }

    float fsd[HID];
#pragma unroll
    for (int h = 0; h < HID; h++) {
        float s = b_fuse[h];
#pragma unroll
        for (int j = 0; j < HID; j++) s += W_fuse[h * 260 + j] * X[j];
        fsd[h] = s + (h == 0 ? l0 : (h == 1 ? l1 : (h == 2 ? l2 : l3)));
    }

    float al = 0.f, be = 0.f, ga = 0.f;
#pragma unroll
    for (int d = 0; d < DQ; d++) {
        float q = b_fc[d];
#pragma unroll
        for (int h = 0; h < HID; h++) q += W_fc[d * HID + h] * fsd[h];
        al += q * W_fc2[d * 2];
        be += q * W_fc2[d * 2 + 1];
        ga += q * b_fc2[d];
    }
    const float NL2E = -1.44269504f;
    g_ABG[r] = make_float4(al * NL2E, be * NL2E, ga * NL2E, 0.f);
}

// ---------------------------------------------------------------------------
// K3: rank-2 sigmoid attention. grid(20, 128) x 128, 4 q/thread.
// Quad-rcp: one rcp serves all 4 queries:
//   R = rcp(d0 d1 d2 d3); r01 = R*p23; r23 = R*p01; pr_i by partial products.
// Per iter: 5 MUFU (4 ex2 + 1 rcp), ~36 FMA-pipe ops.
// ---------------------------------------------------------------------------
__global__ __launch_bounds__(K3THR) void k3_attn() {
    __shared__ float2 suw[KCHUNK];
    int bq  = blockIdx.x;
    int ks  = blockIdx.y;
    int tid = threadIdx.x;
    int b   = bq / (NQB / B_);
    int kbase = b * TN + ks * KCHUNK;

    if (tid < KCHUNK) suw[tid] = g_UW[kbase + tid];
    __syncthreads();

    int r = bq * QBLK + tid * QPT;

    float qa[QPT], qb[QPT], qg[QPT];
#pragma unroll
    for (int i = 0; i < QPT; i++) {
        float4 abg = g_ABG[r + i];
        qa[i] = abg.x; qb[i] = abg.y; qg[i] = abg.z;
    }

    float T0[QPT], T1[QPT], T2[QPT];
#pragma unroll
    for (int i = 0; i < QPT; i++) { T0[i] = 0.f; T1[i] = 0.f; T2[i] = 0.f; }

#pragma unroll 8
    for (int j = 0; j < KCHUNK; j++) {
        float2 uw = suw[j];
        float u = uw.x, w = uw.y;
        float den[QPT];
#pragma unroll
        for (int i = 0; i < QPT; i++) {
            float d = fmaf(qa[i], u, qg[i]);
            d = fmaf(qb[i], w, d);
            den[i] = 1.f + ex2f(d);
        }
        float p01 = den[0] * den[1];
        float p23 = den[2] * den[3];
        float R   = rcpf(p01 * p23);
        float r01 = R * p23;            // = 1/(den0*den1)
        float r23 = R * p01;            // = 1/(den2*den3)
        float pr[QPT];
        pr[0] = den[1] * r01;
        pr[1] = den[0] * r01;
        pr[2] = den[3] * r23;
        pr[3] = den[2] * r23;
#pragma unroll
        for (int i = 0; i < QPT; i++) {
            T0[i] += pr[i];
            T1[i] = fmaf(pr[i], u, T1[i]);
            T2[i] = fmaf(pr[i], w, T2[i]);
        }
    }

    float4* dst = g_part + (size_t)ks * NROWS + r;
#pragma unroll
    for (int i = 0; i < QPT; i++)
        dst[i] = make_float4(T0[i], T1[i], T2[i], 0.f);
}

// ---------------------------------------------------------------------------
// K4: reduce 128 T partials, reconstruct 8-dim, threshold, project. grid(80)x128
// ---------------------------------------------------------------------------
__global__ __launch_bounds__(128) void k4_out(const float* __restrict__ W_fc3,
                                              const float* __restrict__ b_fc3,
                                              const float* __restrict__ W_out,
                                              const float* __restrict__ b_out,
                                              float* __restrict__ out) {
    int r = blockIdx.x * 128 + threadIdx.x;
    if (r >= NROWS) return;

    float S0 = 0.f, S1 = 0.f, S2 = 0.f;
#pragma unroll 8
    for (int ksi = 0; ksi < KSPLIT; ksi++) {
        float4 pp = g_part[(size_t)ksi * NROWS + r];
        S0 += pp.x; S1 += pp.y; S2 += pp.z;
    }

    float s[DQ];
#pragma unroll
    for (int d = 0; d < DQ; d++) {
        float val = W_fc3[d * 2] * S1 + W_fc3[d * 2 + 1] * S2 + b_fc3[d] * S0;
        s[d] = (val > 0.5f) ? val : 0.f;
    }

    int b = r / TN;
    int p = r - b * TN;
    int t = p / V_;
    int v = p - t * V_;

#pragma unroll
    for (int d = 0; d < OUTD; d++) {
        float y = b_out[d];
#pragma unroll
        for (int h = 0; h < DQ; h++) y += W_out[d * DQ + h] * s[h];
        out[((b * OUTD + d) * T_ + t) * V_ + v] = y;
    }
}

// ---------------------------------------------------------------------------
extern "C" void kernel_launch(void* const* d_in, const int* in_sizes, int n_in,
                              void* d_out, int out_size) {
    const float* x       = (const float*)d_in[0];
    const float* coords  = (const float*)d_in[1];
    const float* meta    = (const float*)d_in[2];
    const float* W_ih    = (const float*)d_in[3];
    const float* b_ih    = (const float*)d_in[5];
    const float* b_hh    = (const float*)d_in[6];
    const float* W_comp  = (const float*)d_in[7];
    const float* b_comp  = (const float*)d_in[8];
    const float* W_fuse  = (const float*)d_in[9];
    const float* b_fuse  = (const float*)d_in[10];
    const float* W_fc    = (const float*)d_in[11];
    const float* b_fc    = (const float*)d_in[12];
    const float* W_fc2   = (const float*)d_in[13];
    const float* b_fc2   = (const float*)d_in[14];
    const float* W_fc3   = (const float*)d_in[15];
    const float* b_fc3   = (const float*)d_in[16];
    const float* W_out   = (const float*)d_in[17];
    const float* b_out   = (const float*)d_in[18];
    float* out = (float*)d_out;

    k1f<<<C1SPLIT, 256>>>(W_fuse, W_comp, b_comp, meta);
    k1b_reduce<<<4, 256>>>();
    k2_rows<<<80, 128>>>(x, coords, W_ih, b_ih, b_hh, W_fuse, b_fuse,
                         W_fc, b_fc, W_fc2, b_fc2);
    k3_attn<<<dim3(NQB, KSPLIT), K3THR>>>();
    k4_out<<<80, 128>>>(W_fc3, b_fc3, W_out, b_out, out);
}

// round 12
// speedup vs baseline: 1.1071x; 1.1071x over previous
#include <cuda_runtime.h>
#include <cuda_bf16.h>
#include <math.h>

// ---------------------------------------------------------------------------
#define B_     2
#define T_     20
#define V_     256
#define TN     (T_ * V_)          // 5120
#define NROWS  (B_ * TN)         // 10240
#define HID    4
#define DQ     8
#define OUTD   5
#define CMAP   2048
#define HMAP   32
#define WMAP   32
#define NPIX   (HMAP * WMAP)     // 1024
#define CC     256

#define KSPLIT 64
#define KCHUNK (TN / KSPLIT)     // 80
#define QPT    4                 // queries per thread in k3
#define K3THR  128
#define QBLK   (K3THR * QPT)     // 512
#define NQB    (NROWS / QBLK)    // 20

#define C1SPLIT 64               // channel chunks (32 ch each) in k1f

// ---------------------------------------------------------------------------
__device__ float  g_cb[4];
__device__ float  g_pp[C1SPLIT * 4 * NPIX];
__device__ float4 g_pcomp4[NPIX];
__device__ float4 g_ABG[NROWS];               // (alpha,beta,gamma)*-log2e, pad
__device__ float2 g_UW[NROWS];                // pos-encoded (xr0, xr1)
__device__ float4 g_part[KSPLIT * NROWS];     // (T0,T1,T2,pad) partials

// ---------------------------------------------------------------------------
__device__ __forceinline__ float ex2f(float x) {
    float r; asm("ex2.approx.f32 %0, %1;" : "=f"(r) : "f"(x)); return r;
}
__device__ __forceinline__ float rcpf(float x) {
    float r; asm("rcp.approx.f32 %0, %1;" : "=f"(r) : "f"(x)); return r;
}
__device__ __forceinline__ float fsigm(float x) { return rcpf(1.f + ex2f(-1.44269504f * x)); }
__device__ __forceinline__ float ftanh(float x) { return 1.f - 2.f * rcpf(ex2f(2.88539008f * x) + 1.f); }

// ---------------------------------------------------------------------------
// K1f: fused Weff + pcomp partial. grid(64) x 256.
// ---------------------------------------------------------------------------
__global__ __launch_bounds__(256) void k1f(const float* __restrict__ W_fuse,
                                           const float* __restrict__ W_comp,
                                           const float* __restrict__ b_comp,
                                           const float* __restrict__ metadata) {
    __shared__ float sWfl[4 * 256];   // W_fuse[:, 4:260]
    __shared__ float sW8[8][128];     // per-warp Weff partials
    __shared__ float sw[128];         // Weff[h][cl] for this slice
    int tid = threadIdx.x, ci = blockIdx.x;
    int warp = tid >> 5, lane = tid & 31;

    for (int i = tid; i < 4 * 256; i += 256) {
        int h = i >> 8, cc = i & 255;
        sWfl[i] = W_fuse[h * 260 + 4 + cc];
    }
    __syncthreads();

    {
        float a0 = 0.f, a1 = 0.f, a2 = 0.f, a3 = 0.f;
        const float* base = W_comp + ci * 32 + lane;
#pragma unroll
        for (int k = 0; k < 32; k++) {
            int cc = warp * 32 + k;
            float wv = base[cc * CMAP];
            a0 += sWfl[cc]       * wv;
            a1 += sWfl[256 + cc] * wv;
            a2 += sWfl[512 + cc] * wv;
            a3 += sWfl[768 + cc] * wv;
        }
        sW8[warp][0 * 32 + lane] = a0;
        sW8[warp][1 * 32 + lane] = a1;
        sW8[warp][2 * 32 + lane] = a2;
        sW8[warp][3 * 32 + lane] = a3;
    }
    __syncthreads();

    if (tid < 128) {
        float s = 0.f;
#pragma unroll
        for (int wp = 0; wp < 8; wp++) s += sW8[wp][tid];
        sw[tid] = s;
    }

    if (ci == 0 && warp == 4) {
        float p0 = 0.f, p1 = 0.f, p2 = 0.f, p3 = 0.f;
        for (int cc = lane; cc < CC; cc += 32) {
            float bv = b_comp[cc];
            p0 += sWfl[cc]       * bv;
            p1 += sWfl[256 + cc] * bv;
            p2 += sWfl[512 + cc] * bv;
            p3 += sWfl[768 + cc] * bv;
        }
#pragma unroll
        for (int o = 16; o > 0; o >>= 1) {
            p0 += __shfl_down_sync(0xffffffffu, p0, o);
            p1 += __shfl_down_sync(0xffffffffu, p1, o);
            p2 += __shfl_down_sync(0xffffffffu, p2, o);
            p3 += __shfl_down_sync(0xffffffffu, p3, o);
        }
        if (lane == 0) { g_cb[0] = p0; g_cb[1] = p1; g_cb[2] = p2; g_cb[3] = p3; }
    }
    __syncthreads();

    const float4* m4 = (const float4*)metadata;
    float4 a0 = make_float4(0, 0, 0, 0), a1 = a0, a2 = a0, a3 = a0;
#pragma unroll 8
    for (int cl = 0; cl < 32; cl++) {
        float4 m = m4[(ci * 32 + cl) * 256 + tid];
        float w0 = sw[cl], w1 = sw[32 + cl], w2 = sw[64 + cl], w3 = sw[96 + cl];
        a0.x += w0 * m.x; a0.y += w0 * m.y; a0.z += w0 * m.z; a0.w += w0 * m.w;
        a1.x += w1 * m.x; a1.y += w1 * m.y; a1.z += w1 * m.z; a1.w += w1 * m.w;
        a2.x += w2 * m.x; a2.y += w2 * m.y; a2.z += w2 * m.z; a2.w += w2 * m.w;
        a3.x += w3 * m.x; a3.y += w3 * m.y; a3.z += w3 * m.z; a3.w += w3 * m.w;
    }
    float4* pp4 = (float4*)g_pp;
    pp4[(ci * 4 + 0) * 256 + tid] = a0;
    pp4[(ci * 4 + 1) * 256 + tid] = a1;
    pp4[(ci * 4 + 2) * 256 + tid] = a2;
    pp4[(ci * 4 + 3) * 256 + tid] = a3;
}

// ---------------------------------------------------------------------------
// K1b: reduce 64 partials + bias. grid(4) x 256.
// ---------------------------------------------------------------------------
__global__ __launch_bounds__(256) void k1b_reduce() {
    int pix = blockIdx.x * 256 + threadIdx.x;
    float s0 = g_cb[0], s1 = g_cb[1], s2 = g_cb[2], s3 = g_cb[3];
#pragma unroll 8
    for (int ci = 0; ci < C1SPLIT; ci++) {
        s0 += g_pp[(ci * 4 + 0) * NPIX + pix];
        s1 += g_pp[(ci * 4 + 1) * NPIX + pix];
        s2 += g_pp[(ci * 4 + 2) * NPIX + pix];
        s3 += g_pp[(ci * 4 + 3) * NPIX + pix];
    }
    g_pcomp4[pix] = make_float4(s0, s1, s2, s3);
}

// ---------------------------------------------------------------------------
// K2: per-row pipeline; weights staged in smem, input LDGs hoisted before
// the barrier. grid(80) x 128.
// ---------------------------------------------------------------------------
__global__ __launch_bounds__(128) void k2_rows(
        const float* __restrict__ x,
        const float* __restrict__ coords,
        const float* __restrict__ W_ih,
        const float* __restrict__ b_ih,
        const float* __restrict__ b_hh,
        const float* __restrict__ W_fuse,
        const float* __restrict__ b_fuse,
        const float* __restrict__ W_fc,
        const float* __restrict__ b_fc,
        const float* __restrict__ W_fc2,
        const float* __restrict__ b_fc2) {
    __shared__ float sW_ih[32], sb[16], sWf4[16], sbf[4];
    __shared__ float sW_fc[32], sb_fc[8], sW2a[8], sW2b[8], sb2[8];
    int tid = threadIdx.x;
    int r = blockIdx.x * 128 + tid;
    int b = r / TN;
    int p = r - b * TN;
    int t = p / V_;
    int v = p - t * V_;

    // hoisted input loads (DRAM latency overlaps the staging below)
    float2 xin = ((const float2*)x)[r];
    float cx = coords[((b * 2 + 0) * T_ + t) * V_ + v];
    float cy = coords[((b * 2 + 1) * T_ + t) * V_ + v];

    if (tid < 32) sW_ih[tid] = W_ih[tid];
    if (tid < 16) sb[tid] = b_ih[tid] + b_hh[tid];
    if (tid < 16) sWf4[tid] = W_fuse[(tid >> 2) * 260 + (tid & 3)];
    if (tid < 4)  sbf[tid] = b_fuse[tid];
    if (tid < 32) sW_fc[tid] = W_fc[tid];
    if (tid < 8)  sb_fc[tid] = b_fc[tid];
    if (tid < 8)  sW2a[tid] = W_fc2[tid * 2];
    if (tid < 8)  sW2b[tid] = W_fc2[tid * 2 + 1];
    if (tid < 8)  sb2[tid] = b_fc2[tid];
    __syncthreads();

    float tf  = (float)t;
    float xr0 = xin.x + __sinf(tf);
    float xr1 = xin.y + __cosf(tf);
    g_UW[r] = make_float2(xr0, xr1);

    float X[HID];
#pragma unroll
    for (int h = 0; h < HID; h++) {
        int ji = h, jg = 8 + h, jo = 12 + h;
        float gi = sW_ih[ji * 2] * xr0 + sW_ih[ji * 2 + 1] * xr1 + sb[ji];
        float gg = sW_ih[jg * 2] * xr0 + sW_ih[jg * 2 + 1] * xr1 + sb[jg];
        float go = sW_ih[jo * 2] * xr0 + sW_ih[jo * 2 + 1] * xr1 + sb[jo];
        float cst = fsigm(gi) * ftanh(gg);
        X[h] = fsigm(go) * ftanh(cst);
    }

    float fx = cx * (1.f / 16.f) - 0.5f;
    float fy = cy * (1.f / 16.f) - 0.5f;
    float x0f = floorf(fx), y0f = floorf(fy);
    int ix0 = (int)x0f, iy0 = (int)y0f;
    float wx1 = fx - x0f, wx0 = 1.f - wx1;
    float wy1 = fy - y0f, wy0 = 1.f - wy1;

    float l0 = 0.f, l1 = 0.f, l2 = 0.f, l3 = 0.f;
#pragma unroll
    for (int cyi = 0; cyi < 2; cyi++) {
#pragma unroll
        for (int cxi = 0; cxi < 2; cxi++) {
            int iy = iy0 + cyi, ix = ix0 + cxi;
            if (iy >= 0 && iy < HMAP && ix >= 0 && ix < WMAP) {
                float w = (cyi ? wy1 : wy0) * (cxi ? wx1 : wx0);
                float4 pv = g_pcomp4[iy * WMAP + ix];
                l0 += w * pv.x; l1 += w * pv.y; l2 += w * pv.z; l3 += w * pv.w;
            }
        }
    }

    float fsd[HID];
#pragma unroll
    for (int h = 0; h < HID; h++) {
        float s = sbf[h];
#pragma unroll
        for (int j = 0; j < HID; j++) s += sWf4[h * 4 + j] * X[j];
        fsd[h] = s + (h == 0 ? l0 : (h == 1 ? l1 : (h == 2 ? l2 : l3)));
    }

    float al = 0.f, be = 0.f, ga = 0.f;
#pragma unroll
    for (int d = 0; d < DQ; d++) {
        float q = sb_fc[d];
#pragma unroll
        for (int h = 0; h < HID; h++) q += sW_fc[d * HID + h] * fsd[h];
        al += q * sW2a[d];
        be += q * sW2b[d];
        ga += q * sb2[d];
    }
    const float NL2E = -1.44269504f;
    g_ABG[r] = make_float4(al * NL2E, be * NL2E, ga * NL2E, 0.f);
}

// ---------------------------------------------------------------------------
// K3: rank-2 sigmoid attention. grid(20, 64) x 128, 4 q/thread.
// Quad-rcp: one rcp serves all 4 queries (exact reconstruction via partial
// products). Per iter: 5 MUFU (4 ex2 + 1 rcp), ~33 FMA-pipe ops.
// ---------------------------------------------------------------------------
__global__ __launch_bounds__(K3THR) void k3_attn() {
    __shared__ float2 suw[KCHUNK];
    int bq  = blockIdx.x;
    int ks  = blockIdx.y;
    int tid = threadIdx.x;
    int b   = bq / (NQB / B_);
    int kbase = b * TN + ks * KCHUNK;

    if (tid < KCHUNK) suw[tid] = g_UW[kbase + tid];
    __syncthreads();

    int r = bq * QBLK + tid * QPT;

    float qa[QPT], qb[QPT], qg[QPT];
#pragma unroll
    for (int i = 0; i < QPT; i++) {
        float4 abg = g_ABG[r + i];
        qa[i] = abg.x; qb[i] = abg.y; qg[i] = abg.z;
    }

    float T0[QPT], T1[QPT], T2[QPT];
#pragma unroll
    for (int i = 0; i < QPT; i++) { T0[i] = 0.f; T1[i] = 0.f; T2[i] = 0.f; }

#pragma unroll 8
    for (int j = 0; j < KCHUNK; j++) {
        float2 uw = suw[j];
        float u = uw.x, w = uw.y;
        float den[QPT];
#pragma unroll
        for (int i = 0; i < QPT; i++) {
            float d = fmaf(qa[i], u, qg[i]);
            d = fmaf(qb[i], w, d);
            den[i] = 1.f + ex2f(d);
        }
        float p01 = den[0] * den[1];
        float p23 = den[2] * den[3];
        float R   = rcpf(p01 * p23);
        float r01 = R * p23;            // = 1/(den0*den1)
        float r23 = R * p01;            // = 1/(den2*den3)
        float pr[QPT];
        pr[0] = den[1] * r01;
        pr[1] = den[0] * r01;
        pr[2] = den[3] * r23;
        pr[3] = den[2] * r23;
#pragma unroll
        for (int i = 0; i < QPT; i++) {
            T0[i] += pr[i];
            T1[i] = fmaf(pr[i], u, T1[i]);
            T2[i] = fmaf(pr[i], w, T2[i]);
        }
    }

    float4* dst = g_part + (size_t)ks * NROWS + r;
#pragma unroll
    for (int i = 0; i < QPT; i++)
        dst[i] = make_float4(T0[i], T1[i], T2[i], 0.f);
}

// ---------------------------------------------------------------------------
// K4: reduce 64 T partials, reconstruct 8-dim, threshold, project.
// grid(160) x 64 for latency hiding.
// ---------------------------------------------------------------------------
__global__ __launch_bounds__(64) void k4_out(const float* __restrict__ W_fc3,
                                             const float* __restrict__ b_fc3,
                                             const float* __restrict__ W_out,
                                             const float* __restrict__ b_out,
                                             float* __restrict__ out) {
    int r = blockIdx.x * 64 + threadIdx.x;
    if (r >= NROWS) return;

    float S0 = 0.f, S1 = 0.f, S2 = 0.f;
#pragma unroll 8
    for (int ksi = 0; ksi < KSPLIT; ksi++) {
        float4 pp = g_part[(size_t)ksi * NROWS + r];
        S0 += pp.x; S1 += pp.y; S2 += pp.z;
    }

    float s[DQ];
#pragma unroll
    for (int d = 0; d < DQ; d++) {
        float val = W_fc3[d * 2] * S1 + W_fc3[d * 2 + 1] * S2 + b_fc3[d] * S0;
        s[d] = (val > 0.5f) ? val : 0.f;
    }

    int b = r / TN;
    int p = r - b * TN;
    int t = p / V_;
    int v = p - t * V_;

#pragma unroll
    for (int d = 0; d < OUTD; d++) {
        float y = b_out[d];
#pragma unroll
        for (int h = 0; h < DQ; h++) y += W_out[d * DQ + h] * s[h];
        out[((b * OUTD + d) * T_ + t) * V_ + v] = y;
    }
}

// ---------------------------------------------------------------------------
extern "C" void kernel_launch(void* const* d_in, const int* in_sizes, int n_in,
                              void* d_out, int out_size) {
    const float* x       = (const float*)d_in[0];
    const float* coords  = (const float*)d_in[1];
    const float* meta    = (const float*)d_in[2];
    const float* W_ih    = (const float*)d_in[3];
    const float* b_ih    = (const float*)d_in[5];
    const float* b_hh    = (const float*)d_in[6];
    const float* W_comp  = (const float*)d_in[7];
    const float* b_comp  = (const float*)d_in[8];
    const float* W_fuse  = (const float*)d_in[9];
    const float* b_fuse  = (const float*)d_in[10];
    const float* W_fc    = (const float*)d_in[11];
    const float* b_fc    = (const float*)d_in[12];
    const float* W_fc2   = (const float*)d_in[13];
    const float* b_fc2   = (const float*)d_in[14];
    const float* W_fc3   = (const float*)d_in[15];
    const float* b_fc3   = (const float*)d_in[16];
    const float* W_out   = (const float*)d_in[17];
    const float* b_out   = (const float*)d_in[18];
    float* out = (float*)d_out;

    k1f<<<C1SPLIT, 256>>>(W_fuse, W_comp, b_comp, meta);
    k1b_reduce<<<4, 256>>>();
    k2_rows<<<80, 128>>>(x, coords, W_ih, b_ih, b_hh, W_fuse, b_fuse,
                         W_fc, b_fc, W_fc2, b_fc2);
    k3_attn<<<dim3(NQB, KSPLIT), K3THR>>>();
    k4_out<<<160, 64>>>(W_fc3, b_fc3, W_out, b_out, out);
}